// round 1
// baseline (speedup 1.0000x reference)
#include <cuda_runtime.h>

// RankingLoss over all pairs, N=8192.
// loss = sum_{i,j: dur_i < dur_j, ev_i==1} max(1 - (p_i - p_j), 0) / count, or 0.

#define NN 8192
#define THREADS 128
#define JSPLIT 4
#define JCHUNK (NN / JSPLIT)          // 2048
#define BLOCKS_I (NN / THREADS)       // 64
#define NBLOCKS (BLOCKS_I * JSPLIT)   // 256

__device__ float        g_s[NBLOCKS];
__device__ unsigned int g_c[NBLOCKS];

__global__ void __launch_bounds__(THREADS)
pair_kernel(const float* __restrict__ preds, const float* __restrict__ targets)
{
    __shared__ float2 tile[JCHUNK];          // {dur_j, p_j} interleaved -> one LDS.64/pair

    const int bi = blockIdx.x & (BLOCKS_I - 1);
    const int bj = blockIdx.x >> 6;          // blockIdx.x / BLOCKS_I
    const int i  = bi * THREADS + threadIdx.x;
    const int j0 = bj * JCHUNK;

    // Cooperative load of this block's j-chunk into shared.
    for (int t = threadIdx.x; t < JCHUNK; t += THREADS) {
        const int j = j0 + t;
        tile[t] = make_float2(targets[2 * j], preds[j]);
    }
    __syncthreads();

    const float dur_i = targets[2 * i];
    const float ev_i  = targets[2 * i + 1];
    const float c     = 1.0f - preds[i];     // MARGIN - p_i

    float s = 0.0f;
    unsigned int cnt = 0u;

    if (ev_i == 1.0f) {
        #pragma unroll 8
        for (int t = 0; t < JCHUNK; ++t) {
            const float2 dj = tile[t];
            const bool  m   = dur_i < dj.x;
            const float pen = fmaxf(c + dj.y, 0.0f);
            if (m) { s += pen; cnt += 1u; }
        }
    }

    // Block reduction (deterministic), one partial per block.
    __shared__ float        ss[THREADS];
    __shared__ unsigned int sc[THREADS];
    ss[threadIdx.x] = s;
    sc[threadIdx.x] = cnt;
    __syncthreads();
    #pragma unroll
    for (int o = THREADS / 2; o > 0; o >>= 1) {
        if (threadIdx.x < o) {
            ss[threadIdx.x] += ss[threadIdx.x + o];
            sc[threadIdx.x] += sc[threadIdx.x + o];
        }
        __syncthreads();
    }
    if (threadIdx.x == 0) {
        g_s[blockIdx.x] = ss[0];
        g_c[blockIdx.x] = sc[0];
    }
}

__global__ void __launch_bounds__(NBLOCKS)
final_kernel(float* __restrict__ out)
{
    __shared__ float        ss[NBLOCKS];
    __shared__ unsigned int sc[NBLOCKS];
    const int t = threadIdx.x;
    ss[t] = g_s[t];
    sc[t] = g_c[t];
    __syncthreads();
    #pragma unroll
    for (int o = NBLOCKS / 2; o > 0; o >>= 1) {
        if (t < o) { ss[t] += ss[t + o]; sc[t] += sc[t + o]; }
        __syncthreads();
    }
    if (t == 0) {
        out[0] = (sc[0] > 0u) ? (ss[0] / (float)sc[0]) : 0.0f;
    }
}

extern "C" void kernel_launch(void* const* d_in, const int* in_sizes, int n_in,
                              void* d_out, int out_size)
{
    const float* preds   = (const float*)d_in[0];   // [8192]
    const float* targets = (const float*)d_in[1];   // [8192, 2] row-major {dur, ev}
    float* out = (float*)d_out;

    pair_kernel<<<NBLOCKS, THREADS>>>(preds, targets);
    final_kernel<<<1, NBLOCKS>>>(out);
}

// round 3
// speedup vs baseline: 1.5445x; 1.5445x over previous
#include <cuda_runtime.h>

// RankingLoss over all pairs, N=8192.
// loss = sum_{i,j: dur_i<dur_j, ev_i==1} max(1-(p_i-p_j),0) / count (0 if count==0).
//
// Structure: block = 256 threads owns 256 consecutive i-rows and one j-chunk of 512.
// Block-locally compacts event rows (order-preserving ballot scan -> deterministic),
// so inner-loop warps are fully lane-utilized. Grid (16 j-chunks, 32 i-groups) = 512 blocks.

#define NN 8192
#define TPB 256
#define IG  256                 // i-rows per block
#define JC  512                 // j-cols per block
#define GX  (NN / JC)           // 16 j-chunks
#define GYI (NN / IG)           // 32 i-groups
#define NBLK (GX * GYI)         // 512

__device__ float        g_s[NBLK];
__device__ unsigned int g_c[NBLK];

__global__ void __launch_bounds__(TPB)
pair_kernel(const float* __restrict__ preds, const float* __restrict__ targets)
{
    __shared__ float2 tile[JC];      // {dur_j, p_j}
    __shared__ float  sdur[IG];      // compacted event-row durations
    __shared__ float  scst[IG];      // compacted 1 - p_i
    __shared__ int    wcnt[TPB / 32];
    __shared__ float        rs[TPB];
    __shared__ unsigned int rc[TPB];

    const int tid  = threadIdx.x;
    const int wid  = tid >> 5;
    const int lane = tid & 31;
    const int i    = blockIdx.y * IG + tid;
    const int j0   = blockIdx.x * JC;

    // --- load my i-row, ballot-compact event rows (order preserving) ---
    const float di = targets[2 * i];
    const float ei = targets[2 * i + 1];
    const float pi = preds[i];
    const bool  f  = (ei == 1.0f);
    const unsigned bm = __ballot_sync(0xffffffffu, f);
    if (lane == 0) wcnt[wid] = __popc(bm);

    // --- cooperative j-tile load (overlaps with compaction) ---
    for (int t = tid; t < JC; t += TPB) {
        const int j = j0 + t;
        tile[t] = make_float2(targets[2 * j], preds[j]);
    }
    __syncthreads();

    int base = 0, m = 0;
    #pragma unroll
    for (int w = 0; w < TPB / 32; ++w) {
        const int c = wcnt[w];
        if (w < wid) base += c;
        m += c;
    }
    if (f) {
        const int pos = base + __popc(bm & ((1u << lane) - 1u));
        sdur[pos] = di;
        scst[pos] = 1.0f - pi;
    }
    __syncthreads();

    // --- main loop: threads [0, m) each own one compacted event row ---
    float s0 = 0.0f, s1 = 0.0f, s2 = 0.0f, s3 = 0.0f;
    unsigned int cnt = 0u;
    if (tid < m) {
        const float dur = sdur[tid];
        const float c   = scst[tid];
        for (int t = 0; t < JC; t += 4) {
            const float2 a = tile[t];
            const float2 b = tile[t + 1];
            const float2 d = tile[t + 2];
            const float2 e = tile[t + 3];
            if (dur < a.x) { s0 += fmaxf(c + a.y, 0.0f); cnt++; }
            if (dur < b.x) { s1 += fmaxf(c + b.y, 0.0f); cnt++; }
            if (dur < d.x) { s2 += fmaxf(c + d.y, 0.0f); cnt++; }
            if (dur < e.x) { s3 += fmaxf(c + e.y, 0.0f); cnt++; }
        }
    }

    // --- deterministic block reduction ---
    rs[tid] = (s0 + s1) + (s2 + s3);
    rc[tid] = cnt;
    __syncthreads();
    #pragma unroll
    for (int o = TPB / 2; o > 0; o >>= 1) {
        if (tid < o) { rs[tid] += rs[tid + o]; rc[tid] += rc[tid + o]; }
        __syncthreads();
    }
    if (tid == 0) {
        const int slot = blockIdx.y * GX + blockIdx.x;
        g_s[slot] = rs[0];
        g_c[slot] = rc[0];
    }
}

__global__ void __launch_bounds__(NBLK)
final_kernel(float* __restrict__ out)
{
    __shared__ float        ss[NBLK];
    __shared__ unsigned int sc[NBLK];
    const int t = threadIdx.x;
    ss[t] = g_s[t];
    sc[t] = g_c[t];
    __syncthreads();
    #pragma unroll
    for (int o = NBLK / 2; o > 0; o >>= 1) {
        if (t < o) { ss[t] += ss[t + o]; sc[t] += sc[t + o]; }
        __syncthreads();
    }
    if (t == 0) out[0] = (sc[0] > 0u) ? (ss[0] / (float)sc[0]) : 0.0f;
}

extern "C" void kernel_launch(void* const* d_in, const int* in_sizes, int n_in,
                              void* d_out, int out_size)
{
    const float* preds   = (const float*)d_in[0];   // [8192]
    const float* targets = (const float*)d_in[1];   // [8192,2] {dur, ev}
    float* out = (float*)d_out;

    dim3 grid(GX, GYI);
    pair_kernel<<<grid, TPB>>>(preds, targets);
    final_kernel<<<1, NBLK>>>(out);
}

// round 4
// speedup vs baseline: 1.5633x; 1.0121x over previous
#include <cuda_runtime.h>

// RankingLoss over all pairs, N=8192, single fused kernel.
// loss = sum_{i,j: dur_i<dur_j, ev_i==1} max(1-(p_i-p_j),0) / count (0 if count==0).
//
// Block = 256 threads owns 256 i-rows and one 512-wide j-chunk. Event rows are
// block-locally compacted (order-preserving ballot scan, deterministic). j-tile
// packed as float4 = two {dur,p} pairs -> 1 LDS.128 per 2 pairs. Last-arriving
// block reduces all partials deterministically and writes the output.

#define NN 8192
#define TPB 256
#define IG  256                 // i-rows per block
#define JC  512                 // j-cols per block
#define GX  (NN / JC)           // 16 j-chunks
#define GYI (NN / IG)           // 32 i-groups
#define NBLK (GX * GYI)         // 512

__device__ float        g_s[NBLK];
__device__ unsigned int g_c[NBLK];
__device__ unsigned int g_tick = 0u;

__global__ void __launch_bounds__(TPB)
pair_kernel(const float* __restrict__ preds, const float* __restrict__ targets,
            float* __restrict__ out)
{
    __shared__ float4 tile4[JC / 2];   // {dur_2t, p_2t, dur_2t+1, p_2t+1}
    __shared__ float  sdur[IG];        // compacted event-row durations
    __shared__ float  scst[IG];        // compacted 1 - p_i
    __shared__ int    wcnt[TPB / 32];
    __shared__ float        rs[TPB];
    __shared__ unsigned int rc[TPB];
    __shared__ int    last_flag;

    const int tid  = threadIdx.x;
    const int wid  = tid >> 5;
    const int lane = tid & 31;
    const int i    = blockIdx.y * IG + tid;
    const int j0   = blockIdx.x * JC;

    // --- load my i-row, ballot-compact event rows (order preserving) ---
    const float di = targets[2 * i];
    const float ei = targets[2 * i + 1];
    const float pi = preds[i];
    const bool  f  = (ei == 1.0f);
    const unsigned bm = __ballot_sync(0xffffffffu, f);
    if (lane == 0) wcnt[wid] = __popc(bm);

    // --- cooperative j-tile load (packed float4, overlaps with compaction) ---
    for (int t = tid; t < JC / 2; t += TPB) {
        const int j = j0 + 2 * t;
        tile4[t] = make_float4(targets[2 * j],     preds[j],
                               targets[2 * j + 2], preds[j + 1]);
    }
    __syncthreads();

    int base = 0, m = 0;
    #pragma unroll
    for (int w = 0; w < TPB / 32; ++w) {
        const int c = wcnt[w];
        if (w < wid) base += c;
        m += c;
    }
    if (f) {
        const int pos = base + __popc(bm & ((1u << lane) - 1u));
        sdur[pos] = di;
        scst[pos] = 1.0f - pi;
    }
    __syncthreads();

    // --- main loop: threads [0, m) each own one compacted event row ---
    float s0 = 0.0f, s1 = 0.0f, s2 = 0.0f, s3 = 0.0f;
    unsigned int cnt = 0u;
    if (tid < m) {
        const float dur = sdur[tid];
        const float c   = scst[tid];
        #pragma unroll 2
        for (int t = 0; t < JC / 2; t += 2) {
            const float4 a = tile4[t];
            const float4 b = tile4[t + 1];
            if (dur < a.x) { s0 += fmaxf(c + a.y, 0.0f); cnt++; }
            if (dur < a.z) { s1 += fmaxf(c + a.w, 0.0f); cnt++; }
            if (dur < b.x) { s2 += fmaxf(c + b.y, 0.0f); cnt++; }
            if (dur < b.z) { s3 += fmaxf(c + b.w, 0.0f); cnt++; }
        }
    }

    // --- deterministic block reduction ---
    rs[tid] = (s0 + s1) + (s2 + s3);
    rc[tid] = cnt;
    __syncthreads();
    #pragma unroll
    for (int o = TPB / 2; o > 0; o >>= 1) {
        if (tid < o) { rs[tid] += rs[tid + o]; rc[tid] += rc[tid + o]; }
        __syncthreads();
    }

    // --- publish partial; last-arriving block reduces everything ---
    if (tid == 0) {
        const int slot = blockIdx.y * GX + blockIdx.x;
        g_s[slot] = rs[0];
        g_c[slot] = rc[0];
        __threadfence();
        const unsigned t = atomicAdd(&g_tick, 1u);
        last_flag = (t == NBLK - 1u) ? 1 : 0;
    }
    __syncthreads();

    if (last_flag) {
        // 512 partials -> 256 threads, fixed order: deterministic.
        float        s = g_s[tid] + g_s[tid + TPB];
        unsigned int c = g_c[tid] + g_c[tid + TPB];
        rs[tid] = s;
        rc[tid] = c;
        __syncthreads();
        #pragma unroll
        for (int o = TPB / 2; o > 0; o >>= 1) {
            if (tid < o) { rs[tid] += rs[tid + o]; rc[tid] += rc[tid + o]; }
            __syncthreads();
        }
        if (tid == 0) {
            out[0] = (rc[0] > 0u) ? (rs[0] / (float)rc[0]) : 0.0f;
            g_tick = 0u;   // reset for next graph replay
        }
    }
}

extern "C" void kernel_launch(void* const* d_in, const int* in_sizes, int n_in,
                              void* d_out, int out_size)
{
    const float* preds   = (const float*)d_in[0];   // [8192]
    const float* targets = (const float*)d_in[1];   // [8192,2] {dur, ev}
    float* out = (float*)d_out;

    dim3 grid(GX, GYI);
    pair_kernel<<<grid, TPB>>>(preds, targets, out);
}